// round 2
// baseline (speedup 1.0000x reference)
#include <cuda_runtime.h>
#include <cstdint>

// ---------------------------------------------------------------------------
// EfficientAttention_Mapping: B=256, 2N=4096 (two halves of N=2048), D=3, DK=64
//
// out[b] = normalize( 0.5*(att(x_half0) + att(x_half1)) ), att = mean_n over
// q-softmax(rows) @ [ (k-softmax(cols) ^T v) ].
//
// Exact reformulation accumulated per (b,half):
//   qbar[j]   = sum_n exp(lq[n,j]) / sum_j' exp(lq[n,j'])
//   kden[j]   = sum_n exp(lk[n,j])
//   M[j][e]   = sum_n exp(lk[n,j]) * x[n,e]            (e = 0..2)
// then
//   knum[j][d] = sum_e M[j][e]*Wv[e,d] + bv[d]*kden[j]
//   out_half[d] = (1/N) * sum_j qbar[j] * knum[j][d] / kden[j]
// ---------------------------------------------------------------------------

typedef unsigned long long ull;

__device__ __forceinline__ ull pack2(float lo, float hi) {
    ull r;
    asm("mov.b64 %0, {%1, %2};" : "=l"(r) : "f"(lo), "f"(hi));
    return r;
}
__device__ __forceinline__ void unpack2(ull v, float& lo, float& hi) {
    asm("mov.b64 {%0, %1}, %2;" : "=f"(lo), "=f"(hi) : "l"(v));
}
__device__ __forceinline__ ull fma2(ull a, ull b, ull c) {
    ull d;
    asm("fma.rn.f32x2 %0, %1, %2, %3;" : "=l"(d) : "l"(a), "l"(b), "l"(c));
    return d;
}
__device__ __forceinline__ ull add2(ull a, ull b) {
    ull d;
    asm("add.rn.f32x2 %0, %1, %2;" : "=l"(d) : "l"(a), "l"(b));
    return d;
}
__device__ __forceinline__ float ex2f(float x) {
    float y;
    asm("ex2.approx.ftz.f32 %0, %1;" : "=f"(y) : "f"(x));
    return y;
}
__device__ __forceinline__ float rcpf(float x) {
    float y;
    asm("rcp.approx.ftz.f32 %0, %1;" : "=f"(y) : "f"(x));
    return y;
}

#define LOG2E_F 1.4426950408889634f

// Scratch: 2048 row-blocks x 320 partials (qbar[64], M0[64], M1[64], M2[64], kden[64])
__device__ float g_part[2048 * 320];

// ---------------------------------------------------------------------------
// Kernel 1: each CTA handles 512 consecutive rows of the flattened
// [256*4096, 3] input (block boundaries align exactly with (b, half, split)).
// 256 threads = 32 groups of 8; group handles 16 rows; thread c in a group
// owns 8 j's: j in {c+16u, c+16u+8 : u=0..3} as f32x2 pairs.
// ---------------------------------------------------------------------------
__global__ __launch_bounds__(256)
void ea_accum_kernel(const float* __restrict__ xin,
                     const float* __restrict__ Wq, const float* __restrict__ bq,
                     const float* __restrict__ Wk, const float* __restrict__ bk)
{
    __shared__ float       xs[512 * 3];        // 6 KB: x chunk
    __shared__ ulonglong2  wsu[4][4][8];       // 2 KB: weight pairs, pre-scaled by log2e
    __shared__ float       red[5][8][64];      // 10 KB: end-of-CTA reduction

    const int tid = threadIdx.x;
    const int blk = blockIdx.x;                // 0..2047

    // --- stage x chunk (1536 floats = 384 float4, fully aligned) ---
    {
        const float4* src = reinterpret_cast<const float4*>(xin) + (size_t)blk * 384;
        float4* dst = reinterpret_cast<float4*>(xs);
        #pragma unroll 2
        for (int i = tid; i < 384; i += 256) dst[i] = src[i];
    }

    // --- stage weights: wsu[sp][u][c] holds two f32x2 pairs for j0=c+16u, j1=j0+8
    // sp0: (Wq row0 pair, Wq row1 pair)   sp1: (Wq row2 pair, bq pair)
    // sp2: (Wk row0 pair, Wk row1 pair)   sp3: (Wk row2 pair, bk pair)
    {
        float4* wf = reinterpret_cast<float4*>(&wsu[0][0][0]);
        for (int i = tid; i < 128; i += 256) {
            int c  = i & 7;
            int u  = (i >> 3) & 3;
            int sp = i >> 5;
            int j0 = c + 16 * u, j1 = j0 + 8;
            float a, b, cc, d;
            if (sp == 0)      { a = Wq[j0];       b = Wq[j1];       cc = Wq[64 + j0];  d = Wq[64 + j1]; }
            else if (sp == 1) { a = Wq[128 + j0]; b = Wq[128 + j1]; cc = bq[j0];       d = bq[j1]; }
            else if (sp == 2) { a = Wk[j0];       b = Wk[j1];       cc = Wk[64 + j0];  d = Wk[64 + j1]; }
            else              { a = Wk[128 + j0]; b = Wk[128 + j1]; cc = bk[j0];       d = bk[j1]; }
            wf[i] = make_float4(a * LOG2E_F, b * LOG2E_F, cc * LOG2E_F, d * LOG2E_F);
        }
    }
    __syncthreads();

    const int c = tid & 7;        // j-slice index within group
    const int g = tid >> 3;       // group = row lane (32 groups)

    const ull Z = pack2(0.0f, 0.0f);
    ull qb2[4], M0[4], M1[4], M2a[4], kd2[4];
    #pragma unroll
    for (int u = 0; u < 4; ++u) { qb2[u] = Z; M0[u] = Z; M1[u] = Z; M2a[u] = Z; kd2[u] = Z; }

    #pragma unroll 1
    for (int it = 0; it < 16; ++it) {
        const int row = g + (it << 5);
        const float x0 = xs[row * 3 + 0];
        const float x1 = xs[row * 3 + 1];
        const float x2 = xs[row * 3 + 2];
        const ull X0 = pack2(x0, x0), X1 = pack2(x1, x1), X2 = pack2(x2, x2);

        ull sq2 = Z;
        ull eqs[4];

        #pragma unroll
        for (int u = 0; u < 4; ++u) {
            const ulonglong2 wq01 = wsu[0][u][c];   // (wq0 pair, wq1 pair)
            const ulonglong2 wq2b = wsu[1][u][c];   // (wq2 pair, bq  pair)
            const ulonglong2 wk01 = wsu[2][u][c];
            const ulonglong2 wk2b = wsu[3][u][c];

            ull lq = fma2(X0, wq01.x, fma2(X1, wq01.y, fma2(X2, wq2b.x, wq2b.y)));
            ull lk = fma2(X0, wk01.x, fma2(X1, wk01.y, fma2(X2, wk2b.x, wk2b.y)));

            float a, b;
            unpack2(lq, a, b);
            const ull eq = pack2(ex2f(a), ex2f(b));
            unpack2(lk, a, b);
            const ull ek = pack2(ex2f(a), ex2f(b));

            sq2    = add2(sq2, eq);
            eqs[u] = eq;
            kd2[u] = add2(kd2[u], ek);
            M0[u]  = fma2(ek, X0, M0[u]);
            M1[u]  = fma2(ek, X1, M1[u]);
            M2a[u] = fma2(ek, X2, M2a[u]);
        }

        // row softmax denominator: local pair sum + reduce across 8 threads of group
        float slo, shi;
        unpack2(sq2, slo, shi);
        float sq = slo + shi;
        sq += __shfl_xor_sync(0xffffffffu, sq, 1);
        sq += __shfl_xor_sync(0xffffffffu, sq, 2);
        sq += __shfl_xor_sync(0xffffffffu, sq, 4);
        const float r = rcpf(sq);
        const ull  R = pack2(r, r);

        #pragma unroll
        for (int u = 0; u < 4; ++u) qb2[u] = fma2(eqs[u], R, qb2[u]);
    }

    // --- reduce the 4 groups within each warp (lanes differ by bits 3,4) ---
    #pragma unroll
    for (int u = 0; u < 4; ++u) {
        qb2[u] = add2(qb2[u], __shfl_xor_sync(0xffffffffu, qb2[u], 8));
        qb2[u] = add2(qb2[u], __shfl_xor_sync(0xffffffffu, qb2[u], 16));
        M0[u]  = add2(M0[u],  __shfl_xor_sync(0xffffffffu, M0[u],  8));
        M0[u]  = add2(M0[u],  __shfl_xor_sync(0xffffffffu, M0[u],  16));
        M1[u]  = add2(M1[u],  __shfl_xor_sync(0xffffffffu, M1[u],  8));
        M1[u]  = add2(M1[u],  __shfl_xor_sync(0xffffffffu, M1[u],  16));
        M2a[u] = add2(M2a[u], __shfl_xor_sync(0xffffffffu, M2a[u], 8));
        M2a[u] = add2(M2a[u], __shfl_xor_sync(0xffffffffu, M2a[u], 16));
        kd2[u] = add2(kd2[u], __shfl_xor_sync(0xffffffffu, kd2[u], 8));
        kd2[u] = add2(kd2[u], __shfl_xor_sync(0xffffffffu, kd2[u], 16));
    }

    const int lane = tid & 31;
    const int w    = tid >> 5;
    if (lane < 8) {
        #pragma unroll
        for (int u = 0; u < 4; ++u) {
            const int j0 = lane + 16 * u, j1 = j0 + 8;
            float a, b;
            unpack2(qb2[u], a, b); red[0][w][j0] = a; red[0][w][j1] = b;
            unpack2(M0[u],  a, b); red[1][w][j0] = a; red[1][w][j1] = b;
            unpack2(M1[u],  a, b); red[2][w][j0] = a; red[2][w][j1] = b;
            unpack2(M2a[u], a, b); red[3][w][j0] = a; red[3][w][j1] = b;
            unpack2(kd2[u], a, b); red[4][w][j0] = a; red[4][w][j1] = b;
        }
    }
    __syncthreads();

    for (int vi = tid; vi < 320; vi += 256) {
        const int acc = vi >> 6, j = vi & 63;
        float s = 0.0f;
        #pragma unroll
        for (int ww = 0; ww < 8; ++ww) s += red[acc][ww][j];
        g_part[(size_t)blk * 320 + vi] = s;
    }
}

// ---------------------------------------------------------------------------
// Kernel 2: one CTA per batch (64 threads = j). Combine 4 splits per half,
// apply Wv/bv fold, context division, mean, half-average, L2-normalize.
// ---------------------------------------------------------------------------
__global__ __launch_bounds__(64)
void ea_final_kernel(const float* __restrict__ Wv, const float* __restrict__ bv,
                     float* __restrict__ out)
{
    const int b = blockIdx.x;
    const int j = threadIdx.x;      // 0..63
    __shared__ float sh[2][3];
    __shared__ float ohalf[2][3];

    for (int h = 0; h < 2; ++h) {
        float qb = 0.0f, m0 = 0.0f, m1 = 0.0f, m2 = 0.0f, kd = 0.0f;
        const size_t base = (size_t)((b * 2 + h) * 4) * 320;
        #pragma unroll
        for (int s = 0; s < 4; ++s) {
            const float* p = g_part + base + (size_t)s * 320;
            qb += p[j];
            m0 += p[64 + j];
            m1 += p[128 + j];
            m2 += p[192 + j];
            kd += p[256 + j];
        }
        const float rkd = 1.0f / kd;
        float t[3];
        #pragma unroll
        for (int d = 0; d < 3; ++d) {
            const float kn = m0 * Wv[0 * 3 + d] + m1 * Wv[1 * 3 + d] + m2 * Wv[2 * 3 + d] + bv[d] * kd;
            t[d] = qb * (kn * rkd);
        }
        // reduce over 64 threads: warp reduce then cross-warp via smem
        #pragma unroll
        for (int o = 16; o >= 1; o >>= 1) {
            t[0] += __shfl_xor_sync(0xffffffffu, t[0], o);
            t[1] += __shfl_xor_sync(0xffffffffu, t[1], o);
            t[2] += __shfl_xor_sync(0xffffffffu, t[2], o);
        }
        const int w = j >> 5;
        if ((j & 31) == 0) { sh[w][0] = t[0]; sh[w][1] = t[1]; sh[w][2] = t[2]; }
        __syncthreads();
        if (j == 0) {
            #pragma unroll
            for (int d = 0; d < 3; ++d)
                ohalf[h][d] = (sh[0][d] + sh[1][d]) * (1.0f / 2048.0f);
        }
        __syncthreads();
    }

    if (j == 0) {
        const float a0 = 0.5f * (ohalf[0][0] + ohalf[1][0]);
        const float a1 = 0.5f * (ohalf[0][1] + ohalf[1][1]);
        const float a2 = 0.5f * (ohalf[0][2] + ohalf[1][2]);
        const float inv = rsqrtf(a0 * a0 + a1 * a1 + a2 * a2);
        out[b * 3 + 0] = a0 * inv;
        out[b * 3 + 1] = a1 * inv;
        out[b * 3 + 2] = a2 * inv;
    }
}

// ---------------------------------------------------------------------------
extern "C" void kernel_launch(void* const* d_in, const int* in_sizes, int n_in,
                              void* d_out, int out_size)
{
    const float* xin = (const float*)d_in[0];
    const float* Wq  = (const float*)d_in[1];
    const float* bq  = (const float*)d_in[2];
    const float* Wk  = (const float*)d_in[3];
    const float* bk  = (const float*)d_in[4];
    const float* Wv  = (const float*)d_in[5];
    const float* bv  = (const float*)d_in[6];
    float* out = (float*)d_out;

    ea_accum_kernel<<<2048, 256>>>(xin, Wq, bq, Wk, bk);
    ea_final_kernel<<<256, 64>>>(Wv, bv, out);
}